// round 6
// baseline (speedup 1.0000x reference)
#include <cuda_runtime.h>
#include <math.h>

#define KW   9
#define PAD  4
#define TX   32
#define TY   4
#define PXT  2
#define TW   (TX*PXT)      // 64 output tile width
#define TH   TY            // 4  output tile height
#define SXU  (TW + 2*PAD)  // 72 used smem cols
#define SXP  80            // padded smem row stride
#define SY   (TH + 2*PAD)  // 12 smem rows
#define HH   256
#define WW   256
#define CC   3
#define NVC  18            // float4 cols covering SXU (72/4)

#define INV_DIAG (1.0f / 362.03867196751236f)
#define SIGMA_MIN 0.5f
#define SIGMA_RANGE 9.5f
#define PI_F 3.14159265358979323846f

// rows 0..4 of the symmetric 9x9 q-index map (row oy == row 8-oy)
__device__ constexpr int QIDX5[5][9] = {
    {14,13,12,10, 9,10,12,13,14},
    {13,11, 8, 7, 6, 7, 8,11,13},
    {12, 8, 5, 4, 3, 4, 5, 8,12},
    {10, 7, 4, 2, 1, 2, 4, 7,10},
    { 9, 6, 3, 1, 0, 1, 3, 6, 9},
};

__device__ __forceinline__ int reflect_idx(int v) {
    v = (v < 0) ? -v : v;
    return (v >= HH) ? (2 * HH - 2 - v) : v;   // H == W == 256
}

__device__ __forceinline__ void make_weights(float ddx, float ddy, float* w)
{
    const float d2   = ddx * ddx + ddy * ddy;
    const float dist = sqrtf(d2);
    const float s    = SIGMA_MIN + SIGMA_RANGE * (dist * INV_DIAG);
    const float s2   = s * s;
    const float a    = 0.5f / s2;
    const float common = -dist * sqrtf(s) * __fdividef(1.0f, PI_F * s2 * s2);

    const float E   = __expf(-a);
    const float E2  = E  * E,  E4  = E2  * E2, E5  = E4  * E;
    const float E8  = E4 * E4, E9  = E8  * E,  E10 = E8  * E2;
    const float E13 = E8 * E5, E16 = E8  * E8, E17 = E16 * E;
    const float E18 = E16* E2, E20 = E16 * E4, E25 = E16 * E9;
    const float E32 = E16 * E16;

    w[0]  = common;
    w[1]  = common * fmaf( -1.0f, a, 1.0f) * E;
    w[2]  = common * fmaf( -2.0f, a, 1.0f) * E2;
    w[3]  = common * fmaf( -4.0f, a, 1.0f) * E4;
    w[4]  = common * fmaf( -5.0f, a, 1.0f) * E5;
    w[5]  = common * fmaf( -8.0f, a, 1.0f) * E8;
    w[6]  = common * fmaf( -9.0f, a, 1.0f) * E9;
    w[7]  = common * fmaf(-10.0f, a, 1.0f) * E10;
    w[8]  = common * fmaf(-13.0f, a, 1.0f) * E13;
    w[9]  = common * fmaf(-16.0f, a, 1.0f) * E16;
    w[10] = common * fmaf(-17.0f, a, 1.0f) * E17;
    w[11] = common * fmaf(-18.0f, a, 1.0f) * E18;
    w[12] = common * fmaf(-20.0f, a, 1.0f) * E20;
    w[13] = common * fmaf(-25.0f, a, 1.0f) * E25;
    w[14] = common * fmaf(-32.0f, a, 1.0f) * E32;
}

__global__ __launch_bounds__(TX * TY, 8)
void adaptive_log_conv(const float* __restrict__ x,
                       const float* __restrict__ foa,
                       float* __restrict__ out)
{
    __shared__ __align__(16) float sm[CC][SY][SXP];        // 11.5 KB
    __shared__ __align__(16) float pr[4][CC][TH][SXP];     // 15.4 KB: paired-row sums

    const int b   = blockIdx.z;
    const int bx0 = blockIdx.x * TW;
    const int by0 = blockIdx.y * TH;
    const int lx  = threadIdx.x;
    const int ly  = threadIdx.y;
    const int tid = ly * TX + lx;

    const float* xb = x + (size_t)b * CC * HH * WW;

    // ---- tile load (reflect, no div/mod); latency overlapped by weight gen ----
    const int gy0 = reflect_idx(by0 + ly     - PAD);
    const int gy1 = reflect_idx(by0 + ly + 4 - PAD);
    const int gy2 = reflect_idx(by0 + ly + 8 - PAD);
    const int gx0 = reflect_idx(bx0 + lx      - PAD);
    const int gx1 = reflect_idx(bx0 + lx + 32 - PAD);
    const int gx2 = reflect_idx(bx0 + lx + 64 - PAD);
    const bool has3 = (lx < SXU - 64);

    #pragma unroll
    for (int c = 0; c < CC; c++) {
        const float* xc = xb + c * HH * WW;
        const float* r0 = xc + gy0 * WW;
        const float* r1 = xc + gy1 * WW;
        const float* r2 = xc + gy2 * WW;
        sm[c][ly    ][lx     ] = r0[gx0];
        sm[c][ly    ][lx + 32] = r0[gx1];
        sm[c][ly + 4][lx     ] = r1[gx0];
        sm[c][ly + 4][lx + 32] = r1[gx1];
        sm[c][ly + 8][lx     ] = r2[gx0];
        sm[c][ly + 8][lx + 32] = r2[gx1];
        if (has3) {
            sm[c][ly    ][lx + 64] = r0[gx2];
            sm[c][ly + 4][lx + 64] = r1[gx2];
            sm[c][ly + 8][lx + 64] = r2[gx2];
        }
    }

    // ---- weight generation (overlaps in-flight global loads) ----
    const int px0 = bx0 + PXT * lx;
    const int py  = by0 + ly;
    const float fx  = foa[b * 2 + 0];
    const float fy  = foa[b * 2 + 1];
    const float ddy = (float)py - fy;

    float w0[15], w1[15];
    make_weights((float)(px0    ) - fx, ddy, w0);
    make_weights((float)(px0 + 1) - fx, ddy, w1);

    __syncthreads();

    // ---- paired-row pre-add: pr[a][c][r] = sm[c][r+a] + sm[c][r+8-a] ----
    // total 4*CC*TH*NVC = 864 float4 ops, ~7 per thread
    for (int i = tid; i < 4 * CC * TH * NVC; i += TX * TY) {
        const int a   = i / (CC * TH * NVC);
        int rem       = i - a * (CC * TH * NVC);
        const int ch  = rem / (TH * NVC);
        rem          -= ch * (TH * NVC);
        const int row = rem / NVC;
        const int vc  = (rem - row * NVC) * 4;
        const float4 u = *(const float4*)&sm[ch][row + a    ][vc];
        const float4 v = *(const float4*)&sm[ch][row + 8 - a][vc];
        float4 s;
        s.x = u.x + v.x; s.y = u.y + v.y; s.z = u.z + v.z; s.w = u.w + v.w;
        *(float4*)&pr[a][ch][row][vc] = s;
    }
    __syncthreads();

    // ---- convolution: 5 effective rows per channel (4 paired + middle) ----
    float acc[CC][PXT];
    #pragma unroll
    for (int c = 0; c < CC; c++) { acc[c][0] = 0.0f; acc[c][1] = 0.0f; }

    #pragma unroll
    for (int c = 0; c < CC; c++) {
        #pragma unroll
        for (int a = 0; a < 5; a++) {
            const float* row = (a < 4) ? &pr[a][c][ly][PXT * lx]
                                       : &sm[c][ly + 4][PXT * lx];
            const float2 p0 = *(const float2*)(row + 0);
            const float2 p1 = *(const float2*)(row + 2);
            const float2 p2 = *(const float2*)(row + 4);
            const float2 p3 = *(const float2*)(row + 6);
            const float2 p4 = *(const float2*)(row + 8);
            float t[10];
            t[0] = p0.x; t[1] = p0.y; t[2] = p1.x; t[3] = p1.y;
            t[4] = p2.x; t[5] = p2.y; t[6] = p3.x; t[7] = p3.y;
            t[8] = p4.x; t[9] = p4.y;
            #pragma unroll
            for (int ox = 0; ox < KW; ox++) {
                const int q = QIDX5[a][ox];
                acc[c][0] = fmaf(t[ox    ], w0[q], acc[c][0]);
                acc[c][1] = fmaf(t[ox + 1], w1[q], acc[c][1]);
            }
        }
    }

    float* ob = out + (size_t)b * CC * HH * WW;
    #pragma unroll
    for (int c = 0; c < CC; c++) {
        float2 r;
        r.x = acc[c][0]; r.y = acc[c][1];
        *(float2*)&ob[(c * HH + py) * WW + px0] = r;
    }
}

extern "C" void kernel_launch(void* const* d_in, const int* in_sizes, int n_in,
                              void* d_out, int out_size)
{
    const float* x   = (const float*)d_in[0];
    const float* foa = (const float*)d_in[1];
    float* out = (float*)d_out;

    dim3 block(TX, TY, 1);
    dim3 grid(WW / TW, HH / TH, 4);   // 1024 CTAs
    adaptive_log_conv<<<grid, block>>>(x, foa, out);
}

// round 7
// speedup vs baseline: 1.0208x; 1.0208x over previous
#include <cuda_runtime.h>
#include <math.h>

#define KW   9
#define PAD  4
#define TX   32
#define TY   4
#define PXT  2
#define TW   (TX*PXT)      // 64 output tile width
#define TH   TY            // 4  output tile height
#define SXU  (TW + 2*PAD)  // 72 used smem cols
#define SXP  80            // padded smem row stride
#define SY   (TH + 2*PAD)  // 12 smem rows
#define HH   256
#define WW   256
#define CC   3
#define NV4  18            // float4 cols covering SXU (72/4)

#define INV_DIAG (1.0f / 362.03867196751236f)
#define SIGMA_MIN 0.5f
#define SIGMA_RANGE 9.5f
#define PI_F 3.14159265358979323846f

// rows 0..4 of the symmetric 9x9 q-index map (row oy == row 8-oy)
__device__ constexpr int QIDX5[5][9] = {
    {14,13,12,10, 9,10,12,13,14},
    {13,11, 8, 7, 6, 7, 8,11,13},
    {12, 8, 5, 4, 3, 4, 5, 8,12},
    {10, 7, 4, 2, 1, 2, 4, 7,10},
    { 9, 6, 3, 1, 0, 1, 3, 6, 9},
};

__device__ __forceinline__ int reflect_idx(int v) {
    v = (v < 0) ? -v : v;
    return (v >= HH) ? (2 * HH - 2 - v) : v;   // H == W == 256
}

__device__ __forceinline__ void make_weights(float ddx, float ddy, float* w)
{
    const float d2   = ddx * ddx + ddy * ddy;
    const float dist = sqrtf(d2);
    const float s    = SIGMA_MIN + SIGMA_RANGE * (dist * INV_DIAG);
    const float s2   = s * s;
    const float a    = 0.5f / s2;
    const float common = -dist * sqrtf(s) * __fdividef(1.0f, PI_F * s2 * s2);

    const float E   = __expf(-a);
    const float E2  = E  * E,  E4  = E2  * E2, E5  = E4  * E;
    const float E8  = E4 * E4, E9  = E8  * E,  E10 = E8  * E2;
    const float E13 = E8 * E5, E16 = E8  * E8, E17 = E16 * E;
    const float E18 = E16* E2, E20 = E16 * E4, E25 = E16 * E9;
    const float E32 = E16 * E16;

    w[0]  = common;
    w[1]  = common * fmaf( -1.0f, a, 1.0f) * E;
    w[2]  = common * fmaf( -2.0f, a, 1.0f) * E2;
    w[3]  = common * fmaf( -4.0f, a, 1.0f) * E4;
    w[4]  = common * fmaf( -5.0f, a, 1.0f) * E5;
    w[5]  = common * fmaf( -8.0f, a, 1.0f) * E8;
    w[6]  = common * fmaf( -9.0f, a, 1.0f) * E9;
    w[7]  = common * fmaf(-10.0f, a, 1.0f) * E10;
    w[8]  = common * fmaf(-13.0f, a, 1.0f) * E13;
    w[9]  = common * fmaf(-16.0f, a, 1.0f) * E16;
    w[10] = common * fmaf(-17.0f, a, 1.0f) * E17;
    w[11] = common * fmaf(-18.0f, a, 1.0f) * E18;
    w[12] = common * fmaf(-20.0f, a, 1.0f) * E20;
    w[13] = common * fmaf(-25.0f, a, 1.0f) * E25;
    w[14] = common * fmaf(-32.0f, a, 1.0f) * E32;
}

__global__ __launch_bounds__(TX * TY, 8)
void adaptive_log_conv(const float* __restrict__ x,
                       const float* __restrict__ foa,
                       float* __restrict__ out)
{
    __shared__ __align__(16) float sm[CC][SY][SXP];      // 11.5 KB
    __shared__ __align__(16) float pr[4][CC][TH][SXP];   // 15.4 KB paired-row sums

    const int b   = blockIdx.z;
    const int bx0 = blockIdx.x * TW;
    const int by0 = blockIdx.y * TH;
    const int lx  = threadIdx.x;
    const int ly  = threadIdx.y;     // == warp index (TX == 32)

    const float* xb = x + (size_t)b * CC * HH * WW;

    // ---- tile load (reflect, no div/mod); latency overlapped by weight gen ----
    const int gy0 = reflect_idx(by0 + ly     - PAD);
    const int gy1 = reflect_idx(by0 + ly + 4 - PAD);
    const int gy2 = reflect_idx(by0 + ly + 8 - PAD);
    const int gx0 = reflect_idx(bx0 + lx      - PAD);
    const int gx1 = reflect_idx(bx0 + lx + 32 - PAD);
    const int gx2 = reflect_idx(bx0 + lx + 64 - PAD);
    const bool has3 = (lx < SXU - 64);

    #pragma unroll
    for (int c = 0; c < CC; c++) {
        const float* xc = xb + c * HH * WW;
        const float* r0 = xc + gy0 * WW;
        const float* r1 = xc + gy1 * WW;
        const float* r2 = xc + gy2 * WW;
        sm[c][ly    ][lx     ] = r0[gx0];
        sm[c][ly    ][lx + 32] = r0[gx1];
        sm[c][ly + 4][lx     ] = r1[gx0];
        sm[c][ly + 4][lx + 32] = r1[gx1];
        sm[c][ly + 8][lx     ] = r2[gx0];
        sm[c][ly + 8][lx + 32] = r2[gx1];
        if (has3) {
            sm[c][ly    ][lx + 64] = r0[gx2];
            sm[c][ly + 4][lx + 64] = r1[gx2];
            sm[c][ly + 8][lx + 64] = r2[gx2];
        }
    }

    // ---- weight generation (overlaps in-flight global loads) ----
    const int px0 = bx0 + PXT * lx;
    const int py  = by0 + ly;
    const float fx  = foa[b * 2 + 0];
    const float fy  = foa[b * 2 + 1];
    const float ddy = (float)py - fy;

    float w0[15], w1[15];
    make_weights((float)(px0    ) - fx, ddy, w0);
    make_weights((float)(px0 + 1) - fx, ddy, w1);

    __syncthreads();   // the ONLY block-wide barrier

    // ---- paired-row pre-add, warp-local (warp ly owns pr[*][*][ly][*]) ----
    // compile-time (a,c); lanes 0..17 each handle one float4 column
    if (lx < NV4) {
        const int vc = 4 * lx;
        #pragma unroll
        for (int a = 0; a < 4; a++) {
            #pragma unroll
            for (int c = 0; c < CC; c++) {
                const float4 u = *(const float4*)&sm[c][ly + a    ][vc];
                const float4 v = *(const float4*)&sm[c][ly + 8 - a][vc];
                float4 s;
                s.x = u.x + v.x; s.y = u.y + v.y;
                s.z = u.z + v.z; s.w = u.w + v.w;
                *(float4*)&pr[a][c][ly][vc] = s;
            }
        }
    }
    __syncwarp();      // readers are the same warp that wrote

    // ---- convolution: 5 effective rows per channel (4 paired + middle) ----
    float acc[CC][PXT];
    #pragma unroll
    for (int c = 0; c < CC; c++) { acc[c][0] = 0.0f; acc[c][1] = 0.0f; }

    #pragma unroll
    for (int c = 0; c < CC; c++) {
        #pragma unroll
        for (int a = 0; a < 5; a++) {
            const float* row = (a < 4) ? &pr[a][c][ly][PXT * lx]
                                       : &sm[c][ly + 4][PXT * lx];
            const float2 p0 = *(const float2*)(row + 0);
            const float2 p1 = *(const float2*)(row + 2);
            const float2 p2 = *(const float2*)(row + 4);
            const float2 p3 = *(const float2*)(row + 6);
            const float2 p4 = *(const float2*)(row + 8);
            float t[10];
            t[0] = p0.x; t[1] = p0.y; t[2] = p1.x; t[3] = p1.y;
            t[4] = p2.x; t[5] = p2.y; t[6] = p3.x; t[7] = p3.y;
            t[8] = p4.x; t[9] = p4.y;
            #pragma unroll
            for (int ox = 0; ox < KW; ox++) {
                const int q = QIDX5[a][ox];
                acc[c][0] = fmaf(t[ox    ], w0[q], acc[c][0]);
                acc[c][1] = fmaf(t[ox + 1], w1[q], acc[c][1]);
            }
        }
    }

    float* ob = out + (size_t)b * CC * HH * WW;
    #pragma unroll
    for (int c = 0; c < CC; c++) {
        float2 r;
        r.x = acc[c][0]; r.y = acc[c][1];
        *(float2*)&ob[(c * HH + py) * WW + px0] = r;
    }
}

extern "C" void kernel_launch(void* const* d_in, const int* in_sizes, int n_in,
                              void* d_out, int out_size)
{
    const float* x   = (const float*)d_in[0];
    const float* foa = (const float*)d_in[1];
    float* out = (float*)d_out;

    dim3 block(TX, TY, 1);
    dim3 grid(WW / TW, HH / TH, 4);   // 1024 CTAs
    adaptive_log_conv<<<grid, block>>>(x, foa, out);
}